// round 4
// baseline (speedup 1.0000x reference)
#include <cuda_runtime.h>

// filtfilt (order-4 Butterworth) on x[256][131072].
// Chunked IIR: 256 chunks/row x 512 payload samples, 128-sample warm-up
// (|z_max|~0.888 -> 2.4e-7 state error). Two passes via 67MB scratch in a
// blocked-transposed layout; 2 row-splits of 128 so scratch ~fits L2.
// All global traffic coalesced via smem staging with XOR-swizzled tiles.
// Streaming cache hints (__ldcs/__stcs) protect scratch L2 residency.

#define T_LEN 131072
#define B_ROWS 256
#define RPS 128                 // rows per split
#define PCH 512                 // payload samples per chunk (256*512 == T_LEN)
#define PAD 15                  // 3*(ORDER+1)
#define ROW_F4 (T_LEN / 4)      // 32768 float4 per row of scratch
#define CB_F4 (128 * PCH / 4)   // 16384 float4 per chunk-block
#define SMEM_BYTES 65536        // float4 sm[128][32]

// scratch: y_fwd for one 128-row split, layout [row][cb][phase][j4][c127] (float4)
__device__ __align__(16) float4 g_scr[(size_t)RPS * ROW_F4];
// right-edge forward outputs y(t), t in [15+T_LEN, 15+T_LEN+15)
__device__ float g_edge[RPS][16];

struct Coef {
    float b0, b1, b2, b3, b4;
    float na1, na2, na3, na4;
    float zi0, zi1, zi2, zi3;
};

__device__ __forceinline__ Coef load_coef(const float* __restrict__ bc,
                                          const float* __restrict__ ac) {
    Coef c;
    float b0 = __ldg(bc + 0), b1 = __ldg(bc + 1), b2 = __ldg(bc + 2),
          b3 = __ldg(bc + 3), b4 = __ldg(bc + 4);
    float a1 = __ldg(ac + 1), a2 = __ldg(ac + 2), a3 = __ldg(ac + 3),
          a4 = __ldg(ac + 4);
    // (I - C^T) zi = b[1:] - a[1:]*b0:
    //   (1+a1)z0 - z1 = r0 ; a2 z0 + z1 - z2 = r1 ;
    //   a3 z0 + z2 - z3 = r2 ; a4 z0 + z3 = r3
    float r0 = b1 - a1 * b0, r1 = b2 - a2 * b0, r2 = b3 - a3 * b0,
          r3 = b4 - a4 * b0;
    float s = 1.0f + a1 + a2 + a3 + a4;
    float z0 = (r0 + r1 + r2 + r3) / s;
    float z1 = (1.0f + a1) * z0 - r0;
    float z2 = a2 * z0 + z1 - r1;
    float z3 = a3 * z0 + z2 - r2;
    c.b0 = b0; c.b1 = b1; c.b2 = b2; c.b3 = b3; c.b4 = b4;
    c.na1 = -a1; c.na2 = -a2; c.na3 = -a3; c.na4 = -a4;
    c.zi0 = z0; c.zi1 = z1; c.zi2 = z2; c.zi3 = z3;
    return c;
}

// DF2T order-4 step
#define STEP(xv, yout)                                          \
    do {                                                        \
        yout = fmaf(cf.b0, (xv), z0);                           \
        z0 = fmaf(cf.na1, yout, fmaf(cf.b1, (xv), z1));         \
        z1 = fmaf(cf.na2, yout, fmaf(cf.b2, (xv), z2));         \
        z2 = fmaf(cf.na3, yout, fmaf(cf.b3, (xv), z3));         \
        z3 = fmaf(cf.na4, yout, cf.b4 * (xv));                  \
    } while (0)

// swizzled smem tile: row s (0..127), float4 col j4 (0..31)
#define SM(s, j4) sm[(s) * 32 + ((j4) ^ ((s) & 31))]

__global__ void __launch_bounds__(128)
fwd_kernel(const float* __restrict__ x, const float* __restrict__ bc,
           const float* __restrict__ ac, int row0) {
    extern __shared__ float4 sm[];
    int tid = threadIdx.x, w = tid >> 5, lam = tid & 31;
    int lr = blockIdx.x >> 1, cb = blockIdx.x & 1, c0 = cb << 7;
    int c = c0 + tid;                        // global chunk id in row (0..255)
    Coef cf = load_coef(bc, ac);
    const float* xr = x + (size_t)(row0 + lr) * T_LEN;
    float4* scr = g_scr + (size_t)lr * ROW_F4 + (size_t)cb * CB_F4;

    // ---- warm phase load: segment s <- x[(c0+s)*512 - 128 .. +128) ----
#pragma unroll 8
    for (int k = 0; k < 32; k++) {
        int s = k * 4 + w;
        int off = (c0 + s) * PCH - 128 + lam * 4;
        if (cb == 0 && s == 0) off = 0;      // dummy (chunk 0 has no warm)
        SM(s, lam) = __ldcs(reinterpret_cast<const float4*>(xr + off));
    }
    __syncthreads();

    float z0, z1, z2, z3;
    if (c == 0) {
        // exact: odd-extension preamble t = 0..14, e(t) = 2*x0 - x[15-t]
        float x0 = __ldg(xr);
        float u0 = 2.0f * x0 - __ldg(xr + 15);
        z0 = cf.zi0 * u0; z1 = cf.zi1 * u0; z2 = cf.zi2 * u0; z3 = cf.zi3 * u0;
        for (int t = 0; t < 15; t++) {
            float e = 2.0f * x0 - __ldg(xr + (15 - t));
            float y; STEP(e, y);
        }
    } else {
        float4 v = SM(tid, 0);
        float u0 = v.x;
        z0 = cf.zi0 * u0; z1 = cf.zi1 * u0; z2 = cf.zi2 * u0; z3 = cf.zi3 * u0;
#pragma unroll 4
        for (int j4 = 0; j4 < 32; j4++) {
            v = SM(tid, j4);
            float y;
            STEP(v.x, y); STEP(v.y, y); STEP(v.z, y); STEP(v.w, y);
        }
    }
    __syncthreads();

    // ---- payload phases ----
    for (int f = 0; f < 4; f++) {
#pragma unroll 8
        for (int k = 0; k < 32; k++) {
            int s = k * 4 + w;
            SM(s, lam) = __ldcs(reinterpret_cast<const float4*>(
                xr + (c0 + s) * PCH + f * 128 + lam * 4));
        }
        __syncthreads();
        float4* sb = scr + f * 4096 + tid;
#pragma unroll 4
        for (int j4 = 0; j4 < 32; j4++) {
            float4 v = SM(tid, j4);
            float y0, y1, y2, y3;
            STEP(v.x, y0); STEP(v.y, y1); STEP(v.z, y2); STEP(v.w, y3);
            sb[j4 * 128] = make_float4(y0, y1, y2, y3);   // coalesced across tid
        }
        __syncthreads();
    }

    // ---- right-edge tail (chunk 255): t in [15+T, 15+T+15) ----
    if (cb == 1 && tid == 127) {
        float xl = __ldg(xr + (T_LEN - 1));
        for (int k = 0; k < 15; k++) {
            float e = 2.0f * xl - __ldg(xr + (T_LEN - 2 - k));
            float y; STEP(e, y);
            g_edge[lr][k] = y;
        }
    }
}

__global__ void __launch_bounds__(128)
bwd_kernel(float* __restrict__ out, const float* __restrict__ bc,
           const float* __restrict__ ac, int row0) {
    extern __shared__ float4 sm[];
    int tid = threadIdx.x, w = tid >> 5, lam = tid & 31;
    int lr = blockIdx.x >> 1, cb = blockIdx.x & 1, c0 = cb << 7;
    int c = c0 + tid;
    Coef cf = load_coef(bc, ac);
    const float4* scr = g_scr + (size_t)lr * ROW_F4 + (size_t)cb * CB_F4;
    float* orow = out + (size_t)(row0 + lr) * T_LEN;

    // ---- warm phase load: row tid <- chunk (c+1), phase 0 ----
#pragma unroll 8
    for (int k = 0; k < 32; k++) {
        const float4* p;
        if (tid == 127) {
            p = scr + CB_F4 + (size_t)k * 128;            // next chunk-block, c127=0
            if (cb == 1 && lr == RPS - 1) p = scr;        // dummy (chunk 255)
        } else {
            p = scr + (size_t)k * 128 + tid + 1;
        }
        SM(tid, k) = *p;
    }
    __syncthreads();

    float z0, z1, z2, z3;
    if (c == 255) {
        // exact: start of reversed sequence, 15 edge samples descending
        float u0 = g_edge[lr][14];
        z0 = cf.zi0 * u0; z1 = cf.zi1 * u0; z2 = cf.zi2 * u0; z3 = cf.zi3 * u0;
        for (int k = 14; k >= 0; k--) {
            float y; STEP(g_edge[lr][k], y);
        }
    } else {
        float4 v = SM(tid, 31);
        float u0 = v.w;
        z0 = cf.zi0 * u0; z1 = cf.zi1 * u0; z2 = cf.zi2 * u0; z3 = cf.zi3 * u0;
#pragma unroll 4
        for (int j4 = 31; j4 >= 0; j4--) {
            v = SM(tid, j4);
            float y;
            STEP(v.w, y); STEP(v.z, y); STEP(v.y, y); STEP(v.x, y);
        }
    }
    __syncthreads();

    // ---- payload phases, descending ----
    for (int f = 3; f >= 0; f--) {
#pragma unroll 8
        for (int k = 0; k < 32; k++)                       // linear 64KB tile copy
            SM(tid, k) = __ldcs(scr + f * 4096 + (size_t)k * 128 + tid);
        __syncthreads();
#pragma unroll 4
        for (int j4 = 31; j4 >= 0; j4--) {
            float4 v = SM(tid, j4);
            float p0, p1, p2, p3;
            STEP(v.w, p3); STEP(v.z, p2); STEP(v.y, p1); STEP(v.x, p0);
            SM(tid, j4) = make_float4(p0, p1, p2, p3);     // in-place, own row
        }
        __syncthreads();
#pragma unroll 8
        for (int k = 0; k < 32; k++) {
            int s = k * 4 + w;
            __stcs(reinterpret_cast<float4*>(
                       orow + (c0 + s) * PCH + f * 128 + lam * 4),
                   SM(s, lam));
        }
        __syncthreads();
    }
}

extern "C" void kernel_launch(void* const* d_in, const int* in_sizes, int n_in,
                              void* d_out, int out_size) {
    const float* x = (const float*)d_in[0];
    const float* b = (const float*)d_in[1];
    const float* a = (const float*)d_in[2];
    float* out = (float*)d_out;
    (void)in_sizes; (void)n_in; (void)out_size;

    cudaFuncSetAttribute(fwd_kernel,
                         cudaFuncAttributeMaxDynamicSharedMemorySize, SMEM_BYTES);
    cudaFuncSetAttribute(bwd_kernel,
                         cudaFuncAttributeMaxDynamicSharedMemorySize, SMEM_BYTES);

    for (int r0 = 0; r0 < B_ROWS; r0 += RPS) {
        fwd_kernel<<<RPS * 2, 128, SMEM_BYTES>>>(x, b, a, r0);
        bwd_kernel<<<RPS * 2, 128, SMEM_BYTES>>>(out, b, a, r0);
    }
}

// round 13
// speedup vs baseline: 1.5434x; 1.5434x over previous
#include <cuda_runtime.h>
#include <cstdint>

// filtfilt (order-4 Butterworth) on x[256][131072].
// Chunked IIR, 256 chunks/row x 512 payload, 128-sample warm-up.
// v3: cp.async double-buffered 64-sample subphase pipeline (overlap load
// with compute), 32KB tiles x2 buffers, 2 row-splits of 128 for L2 scratch.

#define T_LEN 131072
#define B_ROWS 256
#define RPS 128                 // rows per split
#define PCH 512                 // payload samples per chunk
#define ROW_F4 (T_LEN / 4)      // 32768 float4 per row of scratch
#define CB_F4 (128 * PCH / 4)   // 16384 float4 per chunk-block
#define TILE_F4 2048            // 128 chunks x 16 float4 (64 samples)
#define SMEM_BYTES (2 * TILE_F4 * 16)   // 65536

__device__ __align__(16) float4 g_scr[(size_t)RPS * ROW_F4];
__device__ float g_edge[RPS][16];

struct Coef {
    float b0, b1, b2, b3, b4;
    float na1, na2, na3, na4;
    float zi0, zi1, zi2, zi3;
};

__device__ __forceinline__ Coef load_coef(const float* __restrict__ bc,
                                          const float* __restrict__ ac) {
    Coef c;
    float b0 = __ldg(bc + 0), b1 = __ldg(bc + 1), b2 = __ldg(bc + 2),
          b3 = __ldg(bc + 3), b4 = __ldg(bc + 4);
    float a1 = __ldg(ac + 1), a2 = __ldg(ac + 2), a3 = __ldg(ac + 3),
          a4 = __ldg(ac + 4);
    float r0 = b1 - a1 * b0, r1 = b2 - a2 * b0, r2 = b3 - a3 * b0,
          r3 = b4 - a4 * b0;
    float s = 1.0f + a1 + a2 + a3 + a4;
    float z0 = (r0 + r1 + r2 + r3) / s;
    float z1 = (1.0f + a1) * z0 - r0;
    float z2 = a2 * z0 + z1 - r1;
    float z3 = a3 * z0 + z2 - r2;
    c.b0 = b0; c.b1 = b1; c.b2 = b2; c.b3 = b3; c.b4 = b4;
    c.na1 = -a1; c.na2 = -a2; c.na3 = -a3; c.na4 = -a4;
    c.zi0 = z0; c.zi1 = z1; c.zi2 = z2; c.zi3 = z3;
    return c;
}

#define STEP(xv, yout)                                          \
    do {                                                        \
        yout = fmaf(cf.b0, (xv), z0);                           \
        z0 = fmaf(cf.na1, yout, fmaf(cf.b1, (xv), z1));         \
        z1 = fmaf(cf.na2, yout, fmaf(cf.b2, (xv), z2));         \
        z2 = fmaf(cf.na3, yout, fmaf(cf.b3, (xv), z3));         \
        z3 = fmaf(cf.na4, yout, cf.b4 * (xv));                  \
    } while (0)

// swizzled tile: buffer bf (0/1), row s (0..127), float4 col j4 (0..15)
#define SM(bf, s, j4) sm[(bf) * TILE_F4 + (s) * 16 + ((j4) ^ ((s) & 15))]

__device__ __forceinline__ void cp16(const float4* smem_dst, const void* gsrc) {
    uint32_t d = (uint32_t)__cvta_generic_to_shared(smem_dst);
    asm volatile("cp.async.cg.shared.global [%0], [%1], 16;" :: "r"(d), "l"(gsrc));
}
__device__ __forceinline__ void cp_commit() {
    asm volatile("cp.async.commit_group;");
}
__device__ __forceinline__ void cp_wait1() {
    asm volatile("cp.async.wait_group 1;");
}
__device__ __forceinline__ void cp_wait0() {
    asm volatile("cp.async.wait_group 0;");
}

// ======================= forward pass =======================
__global__ void __launch_bounds__(128)
fwd_kernel(const float* __restrict__ x, const float* __restrict__ bc,
           const float* __restrict__ ac, int row0) {
    extern __shared__ float4 sm[];
    int tid = threadIdx.x, hw = tid >> 4, lam = tid & 15;
    int lr = blockIdx.x >> 1, cb = blockIdx.x & 1, c0 = cb << 7;
    int c = c0 + tid;
    Coef cf = load_coef(bc, ac);
    const float* xr = x + (size_t)(row0 + lr) * T_LEN;
    float4* scr = g_scr + (size_t)lr * ROW_F4 + (size_t)cb * CB_F4;

    // tile i: i<2 warm (toff=-128,-64), else payload f=i-2 (toff=f*64)
    auto load_tile = [&](int i, int bf) {
        int toff = (i < 2) ? (-128 + i * 64) : ((i - 2) * 64);
#pragma unroll
        for (int k = 0; k < 16; k++) {
            int s = k * 8 + hw;
            long off = (long)(c0 + s) * PCH + toff + lam * 4;
            if (cb == 0 && s == 0 && i < 2) off = 0;     // dummy (chunk 0)
            cp16(&SM(bf, s, lam), xr + off);
        }
        cp_commit();
    };

    float z0 = 0.f, z1 = 0.f, z2 = 0.f, z3 = 0.f;

    auto consume = [&](int i, int bf) {
        if (i < 2) {
            if (c == 0) {
                if (i == 0) {       // exact odd-extension preamble
                    float x0 = __ldg(xr);
                    float u0 = 2.0f * x0 - __ldg(xr + 15);
                    z0 = cf.zi0 * u0; z1 = cf.zi1 * u0;
                    z2 = cf.zi2 * u0; z3 = cf.zi3 * u0;
                    for (int t = 0; t < 15; t++) {
                        float e = 2.0f * x0 - __ldg(xr + (15 - t));
                        float y; STEP(e, y);
                    }
                }
                return;
            }
            if (i == 0) {
                float u0 = SM(bf, tid, 0).x;
                z0 = cf.zi0 * u0; z1 = cf.zi1 * u0;
                z2 = cf.zi2 * u0; z3 = cf.zi3 * u0;
            }
#pragma unroll
            for (int j4 = 0; j4 < 16; j4++) {
                float4 v = SM(bf, tid, j4);
                float y;
                STEP(v.x, y); STEP(v.y, y); STEP(v.z, y); STEP(v.w, y);
            }
        } else {
            int f = i - 2;
            float4* sb = scr + f * TILE_F4 + tid;
#pragma unroll
            for (int j4 = 0; j4 < 16; j4++) {
                float4 v = SM(bf, tid, j4);
                float y0, y1, y2, y3;
                STEP(v.x, y0); STEP(v.y, y1); STEP(v.z, y2); STEP(v.w, y3);
                sb[j4 * 128] = make_float4(y0, y1, y2, y3);
            }
        }
    };

    load_tile(0, 0);
    load_tile(1, 1);
#pragma unroll 1
    for (int i = 0; i < 10; i++) {
        int bf = i & 1;
        if (i + 1 < 10) cp_wait1(); else cp_wait0();
        __syncthreads();
        consume(i, bf);
        __syncthreads();
        if (i + 2 < 10) load_tile(i + 2, bf);
    }

    // right-edge tail: y(t), t in [15+T, 15+T+15)
    if (cb == 1 && tid == 127) {
        float xl = __ldg(xr + (T_LEN - 1));
        for (int k = 0; k < 15; k++) {
            float e = 2.0f * xl - __ldg(xr + (T_LEN - 2 - k));
            float y; STEP(e, y);
            g_edge[lr][k] = y;
        }
    }
}

// ======================= backward pass =======================
__global__ void __launch_bounds__(128)
bwd_kernel(float* __restrict__ out, const float* __restrict__ bc,
           const float* __restrict__ ac, int row0) {
    extern __shared__ float4 sm[];
    int tid = threadIdx.x, hw = tid >> 4, lam = tid & 15;
    int lr = blockIdx.x >> 1, cb = blockIdx.x & 1, c0 = cb << 7;
    int c = c0 + tid;
    Coef cf = load_coef(bc, ac);
    const float4* scr = g_scr + (size_t)lr * ROW_F4 + (size_t)cb * CB_F4;
    float* orow = out + (size_t)(row0 + lr) * T_LEN;

    // tile i: i<2 warm (chunk c+1 subphase f=1-i), else payload f=9-i
    auto load_tile = [&](int i, int bf) {
        if (i < 2) {
            int f = 1 - i;
#pragma unroll
            for (int k = 0; k < 16; k++) {
                const float4* p;
                if (tid == 127) {
                    p = scr + CB_F4 + f * TILE_F4 + (size_t)k * 128;
                    if (cb == 1 && lr == RPS - 1) p = scr;   // dummy (chunk 255)
                } else {
                    p = scr + f * TILE_F4 + (size_t)k * 128 + tid + 1;
                }
                cp16(&SM(bf, tid, k), p);
            }
        } else {
            int f = 9 - i;
#pragma unroll
            for (int k = 0; k < 16; k++)
                cp16(&SM(bf, tid, k), scr + f * TILE_F4 + (size_t)k * 128 + tid);
        }
        cp_commit();
    };

    float z0 = 0.f, z1 = 0.f, z2 = 0.f, z3 = 0.f;

    load_tile(0, 0);
    load_tile(1, 1);
#pragma unroll 1
    for (int i = 0; i < 10; i++) {
        int bf = i & 1;
        if (i + 1 < 10) cp_wait1(); else cp_wait0();
        __syncthreads();
        if (i < 2) {
            // warm: consume descending, no store
            if (c == 255) {
                if (i == 0) {
                    float u0 = g_edge[lr][14];
                    z0 = cf.zi0 * u0; z1 = cf.zi1 * u0;
                    z2 = cf.zi2 * u0; z3 = cf.zi3 * u0;
                    for (int k = 14; k >= 0; k--) {
                        float y; STEP(g_edge[lr][k], y);
                    }
                }
            } else {
                if (i == 0) {
                    float u0 = SM(bf, tid, 15).w;
                    z0 = cf.zi0 * u0; z1 = cf.zi1 * u0;
                    z2 = cf.zi2 * u0; z3 = cf.zi3 * u0;
                }
#pragma unroll
                for (int j4 = 15; j4 >= 0; j4--) {
                    float4 v = SM(bf, tid, j4);
                    float y;
                    STEP(v.w, y); STEP(v.z, y); STEP(v.y, y); STEP(v.x, y);
                }
            }
            __syncthreads();
        } else {
            int f = 9 - i;
            // in-place reversal compute
#pragma unroll
            for (int j4 = 15; j4 >= 0; j4--) {
                float4 v = SM(bf, tid, j4);
                float p0, p1, p2, p3;
                STEP(v.w, p3); STEP(v.z, p2); STEP(v.y, p1); STEP(v.x, p0);
                SM(bf, tid, j4) = make_float4(p0, p1, p2, p3);
            }
            __syncthreads();
            // coalesced store: out[(c0+s)*512 + f*64 + lam*4 ..+4)
#pragma unroll
            for (int k = 0; k < 16; k++) {
                int s = k * 8 + hw;
                __stcs(reinterpret_cast<float4*>(
                           orow + (size_t)(c0 + s) * PCH + f * 64 + lam * 4),
                       SM(bf, s, lam));
            }
            __syncthreads();
        }
        if (i + 2 < 10) load_tile(i + 2, bf);
    }
}

extern "C" void kernel_launch(void* const* d_in, const int* in_sizes, int n_in,
                              void* d_out, int out_size) {
    const float* x = (const float*)d_in[0];
    const float* b = (const float*)d_in[1];
    const float* a = (const float*)d_in[2];
    float* out = (float*)d_out;
    (void)in_sizes; (void)n_in; (void)out_size;

    cudaFuncSetAttribute(fwd_kernel,
                         cudaFuncAttributeMaxDynamicSharedMemorySize, SMEM_BYTES);
    cudaFuncSetAttribute(bwd_kernel,
                         cudaFuncAttributeMaxDynamicSharedMemorySize, SMEM_BYTES);

    for (int r0 = 0; r0 < B_ROWS; r0 += RPS) {
        fwd_kernel<<<RPS * 2, 128, SMEM_BYTES>>>(x, b, a, r0);
        bwd_kernel<<<RPS * 2, 128, SMEM_BYTES>>>(out, b, a, r0);
    }
}